// round 8
// baseline (speedup 1.0000x reference)
#include <cuda_runtime.h>
#include <cuda_bf16.h>
#include <math.h>

// Problem constants
#define BATCH   512
#define DIM     256
#define NTREES  512
#define DEPTH   6
#define UNITS   3
#define NLEAVES 64
#define NCOLS   (NTREES * DEPTH)   // 3072 sparsemax columns
#define MAXC    128                // max sparsemax support per column (padded)

// -------- device scratch (no dynamic allocation allowed) --------
__device__ float  g_xT[DIM * BATCH];       // transposed x: (DIM, BATCH)
__device__ float  g_fslT[NCOLS * DIM];     // transposed fsl: (col, i)
__device__ int    g_nnz[NCOLS];            // PADDED support size (multiple of 8)
__device__ float2 g_sel[NCOLS * MAXC];     // interleaved (idx*BATCH as int bits, weight)
__device__ float  g_gate[NCOLS * BATCH];   // gate values, layout (col, b)

// ============================================================================
// Kernel 0: tiled transposes (pure coalesced bandwidth).
//  blocks [0, 768): fsl (256 i, 3072 col) -> fslT (col, i), 32x32 tiles.
//  blocks [768, 896): x (512 b, 256 i)    -> xT (i, b),     32x32 tiles.
// 256 threads.
// ============================================================================
__global__ void __launch_bounds__(256)
transpose_kernel(const float* __restrict__ x,
                 const float* __restrict__ fsl)
{
    __shared__ float tile[32][33];
    const int bid = blockIdx.x;
    const int tid = threadIdx.x;
    const int tx = tid & 31;
    const int ty = tid >> 5;          // 0..7

    if (bid < 768) {
        // fsl tile: it in [0,8) over i, ct in [0,96) over col
        const int ct = bid % 96;
        const int it = bid / 96;
        #pragma unroll
        for (int r = 0; r < 4; r++) {
            int row = ty + r * 8;     // i within tile
            tile[row][tx] = fsl[(it * 32 + row) * NCOLS + ct * 32 + tx];
        }
        __syncthreads();
        #pragma unroll
        for (int r = 0; r < 4; r++) {
            int row = ty + r * 8;     // col within tile
            g_fslT[(ct * 32 + row) * DIM + it * 32 + tx] = tile[tx][row];
        }
    } else {
        // x tile: bt in [0,16) over batch, it in [0,8) over dim
        const int t  = bid - 768;
        const int bt = t & 15;
        const int it = t >> 4;
        #pragma unroll
        for (int r = 0; r < 4; r++) {
            int row = ty + r * 8;
            tile[row][tx] = x[(bt * 32 + row) * DIM + it * 32 + tx];
        }
        __syncthreads();
        #pragma unroll
        for (int r = 0; r < 4; r++) {
            int row = ty + r * 8;
            g_xT[(it * 32 + row) * BATCH + bt * 32 + tx] = tile[tx][row];
        }
    }
}

// ============================================================================
// Kernel 1: sparsemax, one warp per column, fully coalesced fslT loads.
// 384 blocks x 256 threads (8 warps = 8 columns). No block-level syncs.
// Michelot projection warm-started at tau0 = max(z)-1 (valid: tau* >= zmax-1)
// -> ~2-3 iterations. Output list zero-padded to a multiple of 8.
// ============================================================================
__global__ void __launch_bounds__(256)
sparsemax_kernel()
{
    const int warp = threadIdx.x >> 5;
    const int lane = threadIdx.x & 31;
    const int col  = blockIdx.x * 8 + warp;

    // coalesced: lane reads consecutive addresses, 8 independent loads
    float z[8];
    #pragma unroll
    for (int j = 0; j < 8; j++)
        z[j] = g_fslT[col * DIM + j * 32 + lane];

    // warm start: tau0 = max(z) - 1
    float m = z[0];
    #pragma unroll
    for (int j = 1; j < 8; j++) m = fmaxf(m, z[j]);
    #pragma unroll
    for (int o = 16; o > 0; o >>= 1)
        m = fmaxf(m, __shfl_xor_sync(0xffffffffu, m, o));
    float tau = m - 1.0f;

    // Michelot: tau <- (sum_{z>tau} z - 1)/k until support stable
    int k_prev = -1;
    #pragma unroll 1
    for (int it = 0; it < 16; it++) {
        float s = 0.0f;
        int   k = 0;
        #pragma unroll
        for (int j = 0; j < 8; j++)
            if (z[j] > tau) { s += z[j]; k++; }
        #pragma unroll
        for (int o = 16; o > 0; o >>= 1)
            s += __shfl_xor_sync(0xffffffffu, s, o);
        k = __reduce_add_sync(0xffffffffu, k);
        if (k == k_prev) break;
        k_prev = k;
        tau = (s - 1.0f) / (float)k;
    }

    // compact nonzero weights, interleaved (idx*BATCH, w)
    int base = 0;
    #pragma unroll
    for (int j = 0; j < 8; j++) {
        const bool nz = (z[j] > tau);
        const unsigned mm = __ballot_sync(0xffffffffu, nz);
        if (nz) {
            int pos = base + __popc(mm & ((1u << lane) - 1u));
            g_sel[col * MAXC + pos] =
                make_float2(__int_as_float((j * 32 + lane) * BATCH), z[j] - tau);
        }
        base += __popc(mm);
    }
    // zero-pad to multiple of 8 (idx 0, weight 0 -> harmless in dot)
    const int pad = (base + 7) & ~7;
    if (lane < pad - base)
        g_sel[col * MAXC + base + lane] = make_float2(__int_as_float(0), 0.0f);
    if (lane == 0) g_nnz[col] = pad;
}

// ============================================================================
// Kernel 2: gate[col][b] = sparsemoid((sum_j w_j*xT[idx_j][b] - th)*e^{-lt}).
// One block per column (3072 blocks, 256 threads, 2 b's per thread).
// Branchless 8-entry steps: 16 independent xT loads in flight.
// ============================================================================
__global__ void __launch_bounds__(256)
fv_kernel(const float* __restrict__ th,   // (NTREES, DEPTH) == [col]
          const float* __restrict__ lt)   // (NTREES, DEPTH) == [col]
{
    const int col = blockIdx.x;
    const int tid = threadIdx.x;
    const int cnt = g_nnz[col];           // multiple of 8
    const float2* __restrict__ lst = g_sel + col * MAXC;

    const float thv = __ldg(th + col);
    const float etv = __expf(-__ldg(lt + col));

    float f0 = 0.0f, f1 = 0.0f;
    #pragma unroll 1
    for (int j = 0; j < cnt; j += 8) {
        float2 e[8];
        #pragma unroll
        for (int q = 0; q < 8; q++) e[q] = __ldg(lst + j + q);
        float v0[8], v1[8];
        #pragma unroll
        for (int q = 0; q < 8; q++) {
            int o = __float_as_int(e[q].x);
            v0[q] = g_xT[o + tid];
            v1[q] = g_xT[o + tid + 256];
        }
        #pragma unroll
        for (int q = 0; q < 8; q++) {
            f0 += e[q].y * v0[q];
            f1 += e[q].y * v1[q];
        }
    }
    g_gate[col * BATCH + tid]       = __saturatef(0.5f * ((f0 - thv) * etv) + 0.5f);
    g_gate[col * BATCH + tid + 256] = __saturatef(0.5f * ((f1 - thv) * etv) + 0.5f);
}

// ============================================================================
// Kernel 3: lean forest. 2048 blocks x 128 threads; block = (tree n, b-tile).
// Gates preloaded into registers BEFORE the resp-staging barrier so the LDG
// latency overlaps it. Then factored leaf probs -> response dot.
// ============================================================================
__global__ void __launch_bounds__(128, 12)
forest_kernel(const float* __restrict__ resp,  // (NTREES, UNITS, NLEAVES)
              float* __restrict__ out)         // (BATCH, NTREES, UNITS)
{
    const int n   = blockIdx.x >> 2;
    const int bq  = blockIdx.x & 3;
    const int tid = threadIdx.x;
    const int b   = bq * 128 + tid;

    // issue gate loads first (independent of shared memory)
    float g[DEPTH];
    #pragma unroll
    for (int d = 0; d < DEPTH; d++)
        g[d] = g_gate[(n * DEPTH + d) * BATCH + b];

    __shared__ float4 s_resp4[UNITS * NLEAVES / 4];   // 48 x float4
    if (tid < UNITS * NLEAVES / 4)
        s_resp4[tid] = ((const float4*)resp)[n * (UNITS * NLEAVES / 4) + tid];
    __syncthreads();

    // leaf prob factorization: p_c = qlo[c&7] * qhi[c>>3]
    float qlo[8], qhi[8];
    #pragma unroll
    for (int c = 0; c < 8; c++) {
        float p0 = (c & 1) ? (1.0f - g[0]) : g[0];
        float p1 = (c & 2) ? (1.0f - g[1]) : g[1];
        float p2 = (c & 4) ? (1.0f - g[2]) : g[2];
        qlo[c] = p0 * p1 * p2;
        float p3 = (c & 1) ? (1.0f - g[3]) : g[3];
        float p4 = (c & 2) ? (1.0f - g[4]) : g[4];
        float p5 = (c & 4) ? (1.0f - g[5]) : g[5];
        qhi[c] = p3 * p4 * p5;
    }

    // response contraction
    float acc0 = 0.0f, acc1 = 0.0f, acc2 = 0.0f;
    #pragma unroll
    for (int hi = 0; hi < 8; hi++) {
        const float qh = qhi[hi];
        #pragma unroll
        for (int u = 0; u < UNITS; u++) {
            float4 a = s_resp4[(u * NLEAVES + hi * 8) / 4];
            float4 c = s_resp4[(u * NLEAVES + hi * 8) / 4 + 1];
            float t = a.x * qlo[0] + a.y * qlo[1] + a.z * qlo[2] + a.w * qlo[3]
                    + c.x * qlo[4] + c.y * qlo[5] + c.z * qlo[6] + c.w * qlo[7];
            if (u == 0) acc0 += qh * t;
            else if (u == 1) acc1 += qh * t;
            else acc2 += qh * t;
        }
    }

    float* o = out + ((size_t)b * NTREES + n) * UNITS;
    o[0] = acc0;
    o[1] = acc1;
    o[2] = acc2;
}

// ============================================================================
extern "C" void kernel_launch(void* const* d_in, const int* in_sizes, int n_in,
                              void* d_out, int out_size)
{
    const float* x    = (const float*)d_in[0];  // (512, 256)
    const float* fsl  = (const float*)d_in[1];  // (256, 512, 6)
    const float* th   = (const float*)d_in[2];  // (512, 6)
    const float* lt   = (const float*)d_in[3];  // (512, 6)
    const float* resp = (const float*)d_in[4];  // (512, 3, 64)
    float* out = (float*)d_out;                 // (512, 512, 3)

    transpose_kernel<<<896, 256>>>(x, fsl);
    sparsemax_kernel<<<NCOLS / 8, 256>>>();
    fv_kernel<<<NCOLS, 256>>>(th, lt);
    forest_kernel<<<NTREES * 4, 128>>>(resp, out);
}

// round 9
// speedup vs baseline: 1.1931x; 1.1931x over previous
#include <cuda_runtime.h>
#include <cuda_bf16.h>
#include <math.h>

// Problem constants
#define BATCH   512
#define DIM     256
#define NTREES  512
#define DEPTH   6
#define UNITS   3
#define NLEAVES 64
#define NCOLS   (NTREES * DEPTH)   // 3072 sparsemax columns
#define MAXC    128                // max sparsemax support per column (padded)
#define BT      32                 // forest batch tile
#define NT      16                 // forest tree tile

// -------- device scratch (no dynamic allocation allowed) --------
__device__ float  g_xT[DIM * BATCH];       // transposed x: (DIM, BATCH)
__device__ float  g_fslT[NCOLS * DIM];     // transposed fsl: (col, i)
__device__ int    g_nnz[NCOLS];            // PADDED support size (multiple of 8)
__device__ float2 g_sel[NCOLS * MAXC];     // interleaved (idx*BATCH as int bits, weight)
__device__ float  g_gate[NCOLS * BATCH];   // gate values, layout (col, b)

// ============================================================================
// Kernel 0: tiled transposes (pure coalesced bandwidth).
//  blocks [0, 768): fsl (256 i, 3072 col) -> fslT (col, i), 32x32 tiles.
//  blocks [768, 896): x (512 b, 256 i)    -> xT (i, b),     32x32 tiles.
// ============================================================================
__global__ void __launch_bounds__(256)
transpose_kernel(const float* __restrict__ x,
                 const float* __restrict__ fsl)
{
    __shared__ float tile[32][33];
    const int bid = blockIdx.x;
    const int tid = threadIdx.x;
    const int tx = tid & 31;
    const int ty = tid >> 5;          // 0..7

    if (bid < 768) {
        const int ct = bid % 96;
        const int it = bid / 96;
        #pragma unroll
        for (int r = 0; r < 4; r++) {
            int row = ty + r * 8;
            tile[row][tx] = fsl[(it * 32 + row) * NCOLS + ct * 32 + tx];
        }
        __syncthreads();
        #pragma unroll
        for (int r = 0; r < 4; r++) {
            int row = ty + r * 8;
            g_fslT[(ct * 32 + row) * DIM + it * 32 + tx] = tile[tx][row];
        }
    } else {
        const int t  = bid - 768;
        const int bt = t & 15;
        const int it = t >> 4;
        #pragma unroll
        for (int r = 0; r < 4; r++) {
            int row = ty + r * 8;
            tile[row][tx] = x[(bt * 32 + row) * DIM + it * 32 + tx];
        }
        __syncthreads();
        #pragma unroll
        for (int r = 0; r < 4; r++) {
            int row = ty + r * 8;
            g_xT[(it * 32 + row) * BATCH + bt * 32 + tx] = tile[tx][row];
        }
    }
}

// ============================================================================
// Kernel 1: sparsemax, one warp per column, coalesced fslT loads.
// 384 blocks x 256 threads. Michelot warm-started at tau0 = max(z)-1.
// Output list zero-padded to a multiple of 8.
// ============================================================================
__global__ void __launch_bounds__(256)
sparsemax_kernel()
{
    const int warp = threadIdx.x >> 5;
    const int lane = threadIdx.x & 31;
    const int col  = blockIdx.x * 8 + warp;

    float z[8];
    #pragma unroll
    for (int j = 0; j < 8; j++)
        z[j] = g_fslT[col * DIM + j * 32 + lane];

    float m = z[0];
    #pragma unroll
    for (int j = 1; j < 8; j++) m = fmaxf(m, z[j]);
    #pragma unroll
    for (int o = 16; o > 0; o >>= 1)
        m = fmaxf(m, __shfl_xor_sync(0xffffffffu, m, o));
    float tau = m - 1.0f;

    int k_prev = -1;
    #pragma unroll 1
    for (int it = 0; it < 16; it++) {
        float s = 0.0f;
        int   k = 0;
        #pragma unroll
        for (int j = 0; j < 8; j++)
            if (z[j] > tau) { s += z[j]; k++; }
        #pragma unroll
        for (int o = 16; o > 0; o >>= 1)
            s += __shfl_xor_sync(0xffffffffu, s, o);
        k = __reduce_add_sync(0xffffffffu, k);
        if (k == k_prev) break;
        k_prev = k;
        tau = (s - 1.0f) / (float)k;
    }

    int base = 0;
    #pragma unroll
    for (int j = 0; j < 8; j++) {
        const bool nz = (z[j] > tau);
        const unsigned mm = __ballot_sync(0xffffffffu, nz);
        if (nz) {
            int pos = base + __popc(mm & ((1u << lane) - 1u));
            g_sel[col * MAXC + pos] =
                make_float2(__int_as_float((j * 32 + lane) * BATCH), z[j] - tau);
        }
        base += __popc(mm);
    }
    const int pad = (base + 7) & ~7;
    if (lane < pad - base)
        g_sel[col * MAXC + base + lane] = make_float2(__int_as_float(0), 0.0f);
    if (lane == 0) g_nnz[col] = pad;
}

// ============================================================================
// Kernel 2: gate[col][b] = sparsemoid((sum_j w_j*xT[idx_j][b] - th)*e^{-lt}).
// One block per column (3072 blocks, 256 threads, 2 b's per thread).
// ============================================================================
__global__ void __launch_bounds__(256)
fv_kernel(const float* __restrict__ th,
          const float* __restrict__ lt)
{
    const int col = blockIdx.x;
    const int tid = threadIdx.x;
    const int cnt = g_nnz[col];           // multiple of 8
    const float2* __restrict__ lst = g_sel + col * MAXC;

    const float thv = __ldg(th + col);
    const float etv = __expf(-__ldg(lt + col));

    float f0 = 0.0f, f1 = 0.0f;
    #pragma unroll 1
    for (int j = 0; j < cnt; j += 8) {
        float2 e[8];
        #pragma unroll
        for (int q = 0; q < 8; q++) e[q] = __ldg(lst + j + q);
        float v0[8], v1[8];
        #pragma unroll
        for (int q = 0; q < 8; q++) {
            int o = __float_as_int(e[q].x);
            v0[q] = g_xT[o + tid];
            v1[q] = g_xT[o + tid + 256];
        }
        #pragma unroll
        for (int q = 0; q < 8; q++) {
            f0 += e[q].y * v0[q];
            f1 += e[q].y * v1[q];
        }
    }
    g_gate[col * BATCH + tid]       = __saturatef(0.5f * ((f0 - thv) * etv) + 0.5f);
    g_gate[col * BATCH + tid + 256] = __saturatef(0.5f * ((f1 - thv) * etv) + 0.5f);
}

// ============================================================================
// Kernel 3: tiled forest with COALESCED OUTPUT.
// Block = (32-b x 16-n) tile; 512 blocks x 256 threads.
// tx = b_local (lane), ty covers trees {ty, ty+8}. Gates read coalesced and
// issued before the resp-staging barrier; resp LDS reads are warp-broadcast;
// results staged in smem (stride 49 -> conflict-free) and written as
// contiguous runs per batch row.
// ============================================================================
__global__ void __launch_bounds__(256)
forest_kernel(const float* __restrict__ resp,  // (NTREES, UNITS, NLEAVES)
              float* __restrict__ out)         // (BATCH, NTREES, UNITS)
{
    const int nt  = blockIdx.x & 31;      // 32 n-tiles
    const int btl = blockIdx.x >> 5;      // 16 b-tiles
    const int n0  = nt * NT;
    const int b0  = btl * BT;
    const int tid = threadIdx.x;
    const int tx  = tid & 31;             // b_local
    const int ty  = tid >> 5;             // 0..7

    const int b = b0 + tx;

    // issue all gate loads first (independent of smem staging)
    float gA[DEPTH], gB[DEPTH];
    const int nA = n0 + ty, nB = nA + 8;
    #pragma unroll
    for (int d = 0; d < DEPTH; d++) {
        gA[d] = g_gate[(nA * DEPTH + d) * BATCH + b];
        gB[d] = g_gate[(nB * DEPTH + d) * BATCH + b];
    }

    __shared__ float4 s_resp[NT * 48];           // 16 trees x 192 floats = 12 KB
    __shared__ float  s_out[BT][NT * UNITS + 1]; // 32 x 49, conflict-free

    #pragma unroll
    for (int r = 0; r < 3; r++)
        s_resp[tid + r * 256] = ((const float4*)resp)[n0 * 48 + tid + r * 256];
    __syncthreads();

    #pragma unroll
    for (int pass = 0; pass < 2; pass++) {
        const int n_local = ty + pass * 8;
        const float* g = (pass == 0) ? gA : gB;

        // leaf prob factorization: p_c = qlo[c&7] * qhi[c>>3]
        float qlo[8], qhi[8];
        #pragma unroll
        for (int c = 0; c < 8; c++) {
            float p0 = (c & 1) ? (1.0f - g[0]) : g[0];
            float p1 = (c & 2) ? (1.0f - g[1]) : g[1];
            float p2 = (c & 4) ? (1.0f - g[2]) : g[2];
            qlo[c] = p0 * p1 * p2;
            float p3 = (c & 1) ? (1.0f - g[3]) : g[3];
            float p4 = (c & 2) ? (1.0f - g[4]) : g[4];
            float p5 = (c & 4) ? (1.0f - g[5]) : g[5];
            qhi[c] = p3 * p4 * p5;
        }

        // response contraction (smem reads broadcast across the warp)
        float acc0 = 0.0f, acc1 = 0.0f, acc2 = 0.0f;
        #pragma unroll
        for (int hi = 0; hi < 8; hi++) {
            const float qh = qhi[hi];
            #pragma unroll
            for (int u = 0; u < UNITS; u++) {
                float4 a = s_resp[n_local * 48 + (u * NLEAVES + hi * 8) / 4];
                float4 c = s_resp[n_local * 48 + (u * NLEAVES + hi * 8) / 4 + 1];
                float t = a.x * qlo[0] + a.y * qlo[1] + a.z * qlo[2] + a.w * qlo[3]
                        + c.x * qlo[4] + c.y * qlo[5] + c.z * qlo[6] + c.w * qlo[7];
                if (u == 0) acc0 += qh * t;
                else if (u == 1) acc1 += qh * t;
                else acc2 += qh * t;
            }
        }

        s_out[tx][n_local * UNITS + 0] = acc0;
        s_out[tx][n_local * UNITS + 1] = acc1;
        s_out[tx][n_local * UNITS + 2] = acc2;
    }
    __syncthreads();

    // coalesced write-out: per-b contiguous 48-float (192 B) runs
    #pragma unroll
    for (int r = 0; r < 6; r++) {
        int i   = tid + r * 256;                 // 0 .. 1535
        int row = i / (NT * UNITS);              // b_local
        int c   = i % (NT * UNITS);
        out[(size_t)(b0 + row) * (NTREES * UNITS) + n0 * UNITS + c] = s_out[row][c];
    }
}

// ============================================================================
extern "C" void kernel_launch(void* const* d_in, const int* in_sizes, int n_in,
                              void* d_out, int out_size)
{
    const float* x    = (const float*)d_in[0];  // (512, 256)
    const float* fsl  = (const float*)d_in[1];  // (256, 512, 6)
    const float* th   = (const float*)d_in[2];  // (512, 6)
    const float* lt   = (const float*)d_in[3];  // (512, 6)
    const float* resp = (const float*)d_in[4];  // (512, 3, 64)
    float* out = (float*)d_out;                 // (512, 512, 3)

    transpose_kernel<<<896, 256>>>(x, fsl);
    sparsemax_kernel<<<NCOLS / 8, 256>>>();
    fv_kernel<<<NCOLS, 256>>>(th, lt);
    forest_kernel<<<(BATCH / BT) * (NTREES / NT), 256>>>(resp, out);
}